// round 10
// baseline (speedup 1.0000x reference)
#include <cuda_runtime.h>

// DynamicConv2d: B=64, C=8, H=W=256, OUT_C=8, K=3, pad=1.
// R9: R7's och-pair f32x2 inner loop (proven lowest-aux) + COARSE-GRAIN
//     cp.async pipeline: each CTA owns a 32-row y-strip, processed as 8
//     half-tiles of 4 rows; whole 8-channel sub-tile (26KB) prefetched
//     depth-2 while the previous sub-tile computes (~1150-issue windows).
//     Grid 1024, 3 CTAs/SM, smem 54.5KB dynamic.

typedef unsigned long long u64;

#define TYH 4                    // output rows per half-tile
#define RH 6                     // input rows per half-tile (4 + 2 halo)
#define ST 136                   // row stride (floats); col g at g+4
#define CH (RH * ST)             // 816 floats per channel
#define BUF (8 * CH)             // 6528 floats per sub-tile buffer
#define SMEM_FLOATS (576 + 2 * BUF)
#define SMEM_BYTES (SMEM_FLOATS * 4)   // 54528

// Packed weight scratch: [b][c*9+kk][o], o fastest => och pairs are 8-byte
// aligned LDS.64 after copy to smem.
__device__ __align__(16) float g_wpack[64 * 72 * 8];

__global__ void gen_weights_kernel(const float* __restrict__ dw,
                                   const float* __restrict__ Wg,
                                   const float* __restrict__ bg) {
    int b = blockIdx.x;
    int t = threadIdx.x;          // 0..575
    int j = t >> 3;               // c*9 + kk
    int o = t & 7;                // output channel (torch .view quirk)
    const float* dwp = dw + (b * 8 + o) * 8;
    const float* wgp = Wg + j * 8;
    float v = bg[j];
#pragma unroll
    for (int i = 0; i < 8; i++) v = fmaf(dwp[i], wgp[i], v);
    g_wpack[(b * 72 + j) * 8 + o] = v;
}

__device__ __forceinline__ void cp16(unsigned dst, const void* src, bool pred) {
    int sz = pred ? 16 : 0;
    asm volatile("cp.async.cg.shared.global [%0], [%1], 16, %2;"
                 :: "r"(dst), "l"(src), "r"(sz) : "memory");
}
__device__ __forceinline__ void cp4(unsigned dst, const void* src, bool pred) {
    int sz = pred ? 4 : 0;
    asm volatile("cp.async.ca.shared.global [%0], [%1], 4, %2;"
                 :: "r"(dst), "l"(src), "r"(sz) : "memory");
}
#define CP_COMMIT() asm volatile("cp.async.commit_group;" ::: "memory")

__global__ __launch_bounds__(256, 3)
void conv_kernel(const float* __restrict__ x, float* __restrict__ out) {
    extern __shared__ __align__(16) float sm[];
    float* sw = sm;                                   // 576 packed weights

    int bi = blockIdx.x;
    int b     = bi >> 4;           // batch
    int xh    = bi & 1;            // x half
    int strip = (bi >> 1) & 7;     // 32-row strip
    int x0    = xh * 128;
    int Ybase = strip * 32;

    int tx  = threadIdx.x;         // column within tile 0..127
    int hoo = threadIdx.y;         // och half: 0 -> och 0..3, 1 -> och 4..7
    int tid = tx + (hoo << 7);     // 0..255

    const float* xb = x + (size_t)b * (8 * 65536);
    unsigned sw_s = (unsigned)__cvta_generic_to_shared(sw);
    unsigned bs[2];
    bs[0] = sw_s + 576 * 4;
    bs[1] = bs[0] + BUF * 4;

    // --- sub-tile loader: 8 ch x 6 rows (Y-1..Y+4), interior cp16 + halo cp4
    auto load_half = [&](int Y, unsigned base) {
#pragma unroll
        for (int k = 0; k < 6; k++) {          // 1536 quads / 256 threads
            int i = tid + 256 * k;
            int row = i >> 5;                  // 0..47 = c*6 + t
            int q   = i & 31;
            int c = row / 6;
            int t = row - 6 * c;
            int gy = Y - 1 + t;
            cp16(base + (c * CH + t * ST + 4 * q + 4) * 4,
                 xb + c * 65536 + gy * 256 + x0 + 4 * q,
                 (unsigned)gy < 256u);
        }
        if (tid < 96) {                        // 48 row-slots x 2 sides
            int side = tid >= 48;
            int rr = side ? tid - 48 : tid;
            int c = rr / 6;
            int t = rr - 6 * c;
            int gy = Y - 1 + t;
            int gx = side ? (x0 + 128) : (x0 - 1);
            cp4(base + (c * CH + t * ST + (side ? 132 : 3)) * 4,
                xb + c * 65536 + gy * 256 + gx,
                ((unsigned)gy < 256u) && ((unsigned)gx < 256u));
        }
    };

    // --- prologue: weights + half0 (group 0), half1 (group 1) ---
    if (tid < 144)
        cp16(sw_s + tid * 16, g_wpack + b * 576 + tid * 4, true);
    load_half(Ybase, bs[0]);
    CP_COMMIT();
    load_half(Ybase + 4, bs[1]);
    CP_COMMIT();

    const u64* swq = (const u64*)sw;
    float* ob = out + (size_t)b * (8 * 65536) + x0;

#pragma unroll 1
    for (int h = 0; h < 8; h++) {
        int Y = Ybase + 4 * h;
        if (h < 7) asm volatile("cp.async.wait_group 1;" ::: "memory");
        else       asm volatile("cp.async.wait_group 0;" ::: "memory");
        __syncthreads();           // sub-tile h visible to all threads

        const float* buf = (const float*)(sm + 576 + (h & 1) * BUF);

        u64 acc[TYH][2];
#pragma unroll
        for (int r = 0; r < TYH; r++) { acc[r][0] = 0ull; acc[r][1] = 0ull; }

#pragma unroll 1
        for (int c = 0; c < 8; c++) {
            // 18 natural weight pairs (uniform broadcast LDS.64)
            u64 w[9][2];
#pragma unroll
            for (int kk = 0; kk < 9; kk++) {
#pragma unroll
                for (int p = 0; p < 2; p++)
                    w[kk][p] = swq[(c * 9 + kk) * 4 + hoo * 2 + p];
            }
            const float* sc = buf + c * CH + tx;
#pragma unroll
            for (int t = 0; t < RH; t++) {
                float v0 = sc[t * ST + 3];   // col cx-1
                float v1 = sc[t * ST + 4];   // col cx
                float v2 = sc[t * ST + 5];   // col cx+1
                u64 d0, d1, d2;              // (v,v) splats: 1 MOV each
                asm("mov.b64 %0, {%1, %1};" : "=l"(d0) : "f"(v0));
                asm("mov.b64 %0, {%1, %1};" : "=l"(d1) : "f"(v1));
                asm("mov.b64 %0, {%1, %1};" : "=l"(d2) : "f"(v2));
#pragma unroll
                for (int kh = 0; kh < 3; kh++) {
                    int r = t - kh;          // output row this tap feeds
                    if (r >= 0 && r < TYH) {
#pragma unroll
                        for (int p = 0; p < 2; p++) {
                            asm("fma.rn.f32x2 %0, %1, %2, %0;"
                                : "+l"(acc[r][p]) : "l"(d0), "l"(w[kh * 3 + 0][p]));
                            asm("fma.rn.f32x2 %0, %1, %2, %0;"
                                : "+l"(acc[r][p]) : "l"(d1), "l"(w[kh * 3 + 1][p]));
                            asm("fma.rn.f32x2 %0, %1, %2, %0;"
                                : "+l"(acc[r][p]) : "l"(d2), "l"(w[kh * 3 + 2][p]));
                        }
                    }
                }
            }
        }

        // --- write out 4 rows (register-only; safe before the sync) ---
#pragma unroll
        for (int r = 0; r < TYH; r++) {
#pragma unroll
            for (int p = 0; p < 2; p++) {
                int q = hoo * 2 + p;
                unsigned lo, hi;
                asm("mov.b64 {%0, %1}, %2;" : "=r"(lo), "=r"(hi) : "l"(acc[r][p]));
                ob[(2 * q + 0) * 65536 + (Y + r) * 256 + tx] = __uint_as_float(lo);
                ob[(2 * q + 1) * 65536 + (Y + r) * 256 + tx] = __uint_as_float(hi);
            }
        }

        __syncthreads();           // all threads done reading buf[h&1]
        if (h < 6) {
            load_half(Ybase + 4 * (h + 2), bs[h & 1]);
            CP_COMMIT();
        }
    }
}

extern "C" void kernel_launch(void* const* d_in, const int* in_sizes, int n_in,
                              void* d_out, int out_size) {
    const float* x  = (const float*)d_in[0];
    const float* dw = (const float*)d_in[1];
    const float* Wg = (const float*)d_in[2];
    const float* bg = (const float*)d_in[3];
    float* out = (float*)d_out;

    cudaFuncSetAttribute(conv_kernel, cudaFuncAttributeMaxDynamicSharedMemorySize,
                         SMEM_BYTES);

    gen_weights_kernel<<<64, 576>>>(dw, Wg, bg);

    dim3 blk(128, 2, 1);
    conv_kernel<<<1024, blk, SMEM_BYTES>>>(x, out);
}

// round 11
// speedup vs baseline: 1.2321x; 1.2321x over previous
#include <cuda_runtime.h>

// DynamicConv2d: B=64, C=8, H=W=256, OUT_C=8, K=3, pad=1.
// R10: FAT THREADS — 128 threads/CTA, each thread computes 1 column x 8 rows
//      x ALL 8 output channels (4 f32x2 och-pairs). Raises FFMA2 fraction of
//      the issue stream from 61% to 75%; ILP (36 independent FFMA2 per input
//      splat-trio) hides LDS latency. R7's proven monolithic loader.
//      __launch_bounds__(128,3): 166-reg budget, 3 CTAs/SM.

typedef unsigned long long u64;

#define TY 8                    // output rows per tile
#define TX 128                  // output cols per tile
#define SIN_STRIDE 136          // row stride (floats); col g stored at g+4
#define SIN_ROWS (TY + 2)       // 10
#define SIN_PER_C (SIN_ROWS * SIN_STRIDE)     // 1360
#define SMEM_W 576              // packed weights: 72*8
#define SMEM_FLOATS (SMEM_W + 8 * SIN_PER_C)  // 11456
#define SMEM_BYTES (SMEM_FLOATS * 4)          // 45824

// Packed weight scratch: [b][c*9+kk][o], o fastest => och pairs are 8-byte
// aligned LDS.64 after copy to smem.
__device__ __align__(16) float g_wpack[64 * 72 * 8];

__global__ void gen_weights_kernel(const float* __restrict__ dw,
                                   const float* __restrict__ Wg,
                                   const float* __restrict__ bg) {
    int b = blockIdx.x;
    int t = threadIdx.x;          // 0..575
    int j = t >> 3;               // c*9 + kk
    int o = t & 7;                // output channel (torch .view quirk)
    const float* dwp = dw + (b * 8 + o) * 8;
    const float* wgp = Wg + j * 8;
    float v = bg[j];
#pragma unroll
    for (int i = 0; i < 8; i++) v = fmaf(dwp[i], wgp[i], v);
    g_wpack[(b * 72 + j) * 8 + o] = v;
}

__global__ __launch_bounds__(128, 3)
void conv_kernel(const float* __restrict__ x, float* __restrict__ out) {
    extern __shared__ float sm[];
    float* sw  = sm;               // 576 floats packed weights
    float* sin = sm + SMEM_W;      // 8 ch x 10 rows x 136; col g at g+4

    int bi = blockIdx.x;
    int b  = bi >> 6;              // batch
    int y0 = ((bi >> 1) & 31) * TY;
    int x0 = (bi & 1) * TX;
    int tx = threadIdx.x;          // column within tile 0..127

    // --- weights: 576 floats = 144 float4 ---
    if (tx < 128) {
        const float4* wsrc = (const float4*)(g_wpack + b * 576);
        ((float4*)sw)[tx] = wsrc[tx];
        if (tx < 16) ((float4*)sw)[tx + 128] = wsrc[tx + 128];
    }

    // --- input tile: LDG.128 + aligned STS.128 (col g at index g+4) ---
    const float* xb = x + (size_t)b * (8 * 65536);
    {
        int w5 = tx >> 5;          // 0..3
        int q  = tx & 31;          // quad 0..31
#pragma unroll
        for (int pass = 0; pass < 20; pass++) {
            int row = pass * 4 + w5;      // 0..79 = c*10 + t
            int c = row / 10;
            int t = row - c * 10;
            int gy = y0 - 1 + t;
            float4 v = make_float4(0.f, 0.f, 0.f, 0.f);
            if ((unsigned)gy < 256u)
                v = *(const float4*)(xb + c * 65536 + gy * 256 + x0 + 4 * q);
            *(float4*)(sin + row * SIN_STRIDE + 4 * q + 4) = v;
        }
        // halo: left (x0-1) -> idx 3, right (x0+128) -> idx 132
#pragma unroll
        for (int side = 0; side < 2; side++) {
            if (tx < 80) {
                int c = tx / 10;
                int t = tx - c * 10;
                int gy = y0 - 1 + t;
                int gx = side ? (x0 + 128) : (x0 - 1);
                float v = 0.f;
                if (((unsigned)gy < 256u) && ((unsigned)gx < 256u))
                    v = __ldg(xb + c * 65536 + gy * 256 + gx);
                sin[tx * SIN_STRIDE + (side ? 132 : 3)] = v;
            }
        }
    }
    __syncthreads();

    // --- accumulate: acc[r][q] packs och (2q, 2q+1) for this column ---
    u64 acc[TY][4];
#pragma unroll
    for (int r = 0; r < TY; r++)
#pragma unroll
        for (int q = 0; q < 4; q++) acc[r][q] = 0ull;

    const u64* swq = (const u64*)sw;

#pragma unroll 1
    for (int c = 0; c < 8; c++) {
        // 36 natural weight pairs for ALL 8 och (uniform broadcast LDS.64)
        u64 w[9][4];
#pragma unroll
        for (int kk = 0; kk < 9; kk++) {
#pragma unroll
            for (int q = 0; q < 4; q++)
                w[kk][q] = swq[(c * 9 + kk) * 4 + q];
        }
        const float* sc = sin + c * SIN_PER_C + tx;
#pragma unroll
        for (int t = 0; t < SIN_ROWS; t++) {
            float v0 = sc[t * SIN_STRIDE + 3];   // col cx-1
            float v1 = sc[t * SIN_STRIDE + 4];   // col cx
            float v2 = sc[t * SIN_STRIDE + 5];   // col cx+1
            u64 d0, d1, d2;                      // (v,v) splats
            asm("mov.b64 %0, {%1, %1};" : "=l"(d0) : "f"(v0));
            asm("mov.b64 %0, {%1, %1};" : "=l"(d1) : "f"(v1));
            asm("mov.b64 %0, {%1, %1};" : "=l"(d2) : "f"(v2));
#pragma unroll
            for (int kh = 0; kh < 3; kh++) {
                int r = t - kh;                  // output row this tap feeds
                if (r >= 0 && r < TY) {
#pragma unroll
                    for (int q = 0; q < 4; q++) {
                        asm("fma.rn.f32x2 %0, %1, %2, %0;"
                            : "+l"(acc[r][q]) : "l"(d0), "l"(w[kh * 3 + 0][q]));
                        asm("fma.rn.f32x2 %0, %1, %2, %0;"
                            : "+l"(acc[r][q]) : "l"(d1), "l"(w[kh * 3 + 1][q]));
                        asm("fma.rn.f32x2 %0, %1, %2, %0;"
                            : "+l"(acc[r][q]) : "l"(d2), "l"(w[kh * 3 + 2][q]));
                    }
                }
            }
        }
    }

    // --- write out: acc[r][q] = (och 2q, och 2q+1), scalar STG each ---
    float* ob = out + (size_t)b * (8 * 65536) + x0;
#pragma unroll
    for (int r = 0; r < TY; r++) {
#pragma unroll
        for (int q = 0; q < 4; q++) {
            unsigned lo, hi;
            asm("mov.b64 {%0, %1}, %2;" : "=r"(lo), "=r"(hi) : "l"(acc[r][q]));
            ob[(2 * q + 0) * 65536 + (y0 + r) * 256 + tx] = __uint_as_float(lo);
            ob[(2 * q + 1) * 65536 + (y0 + r) * 256 + tx] = __uint_as_float(hi);
        }
    }
}

extern "C" void kernel_launch(void* const* d_in, const int* in_sizes, int n_in,
                              void* d_out, int out_size) {
    const float* x  = (const float*)d_in[0];
    const float* dw = (const float*)d_in[1];
    const float* Wg = (const float*)d_in[2];
    const float* bg = (const float*)d_in[3];
    float* out = (float*)d_out;

    cudaFuncSetAttribute(conv_kernel, cudaFuncAttributeMaxDynamicSharedMemorySize,
                         SMEM_BYTES);

    gen_weights_kernel<<<64, 576>>>(dw, Wg, bg);

    conv_kernel<<<64 * 32 * 2, 128, SMEM_BYTES>>>(x, out);
}